// round 1
// baseline (speedup 1.0000x reference)
#include <cuda_runtime.h>

// LSTM: B=4096, T=512, IN=1, H=32, OUT=1
// One CTA of 128 threads per batch element.
// Thread g (g = wid*32+lane) computes gate row g each step (warp = gate type).
// Each warp redundantly maintains the full (h, c) state: lane j of every warp
// owns c_j and h_j, so only ONE __syncthreads (gate exchange) is needed per step.

#define BB 4096
#define TT 512
#define HH 32

__device__ __forceinline__ float sigmoid_f(float x) {
    return 1.0f / (1.0f + __expf(-x));
}
__device__ __forceinline__ float tanh_f(float x) {
    // 2*sigmoid(2x)-1 ; saturates correctly for |x| large (expf -> inf/0)
    return 2.0f / (1.0f + __expf(-2.0f * x)) - 1.0f;
}

__global__ __launch_bounds__(128)
void lstm_fp32_kernel(const float* __restrict__ x,      // [B,T,1]
                      const float* __restrict__ W_ih,   // [4H,1]
                      const float* __restrict__ W_hh,   // [4H,H]
                      const float* __restrict__ b_ih,   // [4H]
                      const float* __restrict__ b_hh,   // [4H]
                      const float* __restrict__ fc_w,   // [1,H]
                      const float* __restrict__ fc_b,   // [1]
                      float* __restrict__ out)          // [B,1]
{
    __shared__ float  x_sh[TT];
    __shared__ float4 h_sh[4][HH / 4];       // per-warp replicated h (32 floats each)
    __shared__ float  gates_sh[2][4][HH];    // double-buffered gate exchange

    const int tid  = threadIdx.x;
    const int wid  = tid >> 5;
    const int lane = tid & 31;
    const int b    = blockIdx.x;

    // Stage this batch element's x sequence into shared (coalesced).
    const float* xb = x + (size_t)b * TT;
    #pragma unroll
    for (int i = 0; i < TT / 128; i++)
        x_sh[tid + i * 128] = xb[tid + i * 128];

    // Per-thread W_hh row -> registers (one-time, L2-resident across all CTAs).
    float w[HH];
    const float4* wrow = reinterpret_cast<const float4*>(W_hh + tid * HH);
    #pragma unroll
    for (int q = 0; q < HH / 4; q++) {
        float4 v = wrow[q];
        w[4 * q + 0] = v.x; w[4 * q + 1] = v.y;
        w[4 * q + 2] = v.z; w[4 * q + 3] = v.w;
    }
    const float wih  = W_ih[tid];
    const float bias = b_ih[tid] + b_hh[tid];

    // h, c init = 0
    if (lane < HH / 4) h_sh[wid][lane] = make_float4(0.f, 0.f, 0.f, 0.f);
    float c  = 0.0f;
    float hj = 0.0f;
    __syncthreads();

    int p = 0;
    for (int t = 0; t < TT; t++) {
        // gate preactivation: x_t * W_ih[g] + bias[g] + dot(h, W_hh[g,:])
        const float xt = x_sh[t];
        float acc0 = fmaf(xt, wih, bias);
        float acc1 = 0.f, acc2 = 0.f, acc3 = 0.f;
        #pragma unroll
        for (int q = 0; q < HH / 4; q++) {
            float4 hv = h_sh[wid][q];   // broadcast LDS.128, conflict-free
            acc0 = fmaf(hv.x, w[4 * q + 0], acc0);
            acc1 = fmaf(hv.y, w[4 * q + 1], acc1);
            acc2 = fmaf(hv.z, w[4 * q + 2], acc2);
            acc3 = fmaf(hv.w, w[4 * q + 3], acc3);
        }
        const float pre = (acc0 + acc1) + (acc2 + acc3);

        // warp-uniform activation: warps 0,1,3 -> sigmoid (i,f,o); warp 2 -> tanh (g)
        float a;
        if (wid == 2) a = tanh_f(pre);
        else          a = sigmoid_f(pre);

        gates_sh[p][wid][lane] = a;
        __syncthreads();   // the ONLY block barrier per step

        const float gi = gates_sh[p][0][lane];
        const float gf = gates_sh[p][1][lane];
        const float gg = gates_sh[p][2][lane];
        const float go = gates_sh[p][3][lane];

        // every warp redundantly updates its own replica of (c_j, h_j)
        c  = fmaf(gf, c, gi * gg);
        hj = go * tanh_f(c);

        reinterpret_cast<float*>(h_sh[wid])[lane] = hj;  // own warp's row only
        p ^= 1;
        __syncwarp();      // order h write before next iteration's read (same warp)
    }

    // Output: out[b] = dot(h, fc_w) + fc_b ; warp 0 reduces its replica.
    if (wid == 0) {
        float v = hj * fc_w[lane];
        #pragma unroll
        for (int off = 16; off > 0; off >>= 1)
            v += __shfl_xor_sync(0xffffffffu, v, off);
        if (lane == 0) out[b] = v + fc_b[0];
    }
}

extern "C" void kernel_launch(void* const* d_in, const int* in_sizes, int n_in,
                              void* d_out, int out_size) {
    const float* x    = (const float*)d_in[0];
    const float* W_ih = (const float*)d_in[1];
    const float* W_hh = (const float*)d_in[2];
    const float* b_ih = (const float*)d_in[3];
    const float* b_hh = (const float*)d_in[4];
    const float* fc_w = (const float*)d_in[5];
    const float* fc_b = (const float*)d_in[6];
    float* out = (float*)d_out;

    lstm_fp32_kernel<<<BB, 128>>>(x, W_ih, W_hh, b_ih, b_hh, fc_w, fc_b, out);
}

// round 2
// speedup vs baseline: 1.7111x; 1.7111x over previous
#include <cuda_runtime.h>

// LSTM: B=4096, T=512, IN=1, H=32, OUT=1
// One WARP per batch element; 128-thread CTAs hold 4 independent warps.
// Lane j computes gate rows i_j, f_j, g_j, o_j (4x32 W_hh weights in registers,
// FMAs packed 2-wide with fma.rn.f32x2). Gates never leave registers; only h
// (32 floats) goes through per-warp smem, double-buffered -> 1 __syncwarp/step.

#define TT 512
#define HH 32

typedef unsigned long long u64;

__device__ __forceinline__ u64 fma2(u64 a, u64 b, u64 c) {
    u64 d;
    asm("fma.rn.f32x2 %0, %1, %2, %3;" : "=l"(d) : "l"(a), "l"(b), "l"(c));
    return d;
}
__device__ __forceinline__ u64 add2(u64 a, u64 b) {
    u64 d;
    asm("add.rn.f32x2 %0, %1, %2;" : "=l"(d) : "l"(a), "l"(b));
    return d;
}
__device__ __forceinline__ float unpack_sum(u64 v) {
    float lo, hi;
    asm("mov.b64 {%0, %1}, %2;" : "=f"(lo), "=f"(hi) : "l"(v));
    return lo + hi;
}
// sigmoid(x) = 1/(1+2^(-x*log2e)) : FMUL + MUFU.EX2 + FADD + MUFU.RCP
__device__ __forceinline__ float sigf(float x) {
    float e, r;
    asm("ex2.approx.f32 %0, %1;" : "=f"(e) : "f"(-1.4426950408889634f * x));
    asm("rcp.approx.f32 %0, %1;" : "=f"(r) : "f"(1.0f + e));
    return r;
}
// tanh(x) = 2*sigmoid(2x) - 1
__device__ __forceinline__ float tanhx(float x) {
    float e, r;
    asm("ex2.approx.f32 %0, %1;" : "=f"(e) : "f"(-2.8853900817779268f * x));
    asm("rcp.approx.f32 %0, %1;" : "=f"(r) : "f"(1.0f + e));
    return fmaf(2.0f, r, -1.0f);
}

__global__ __launch_bounds__(128)
void lstm_warp_kernel(const float* __restrict__ x,      // [B,T,1]
                      const float* __restrict__ W_ih,   // [4H,1]
                      const float* __restrict__ W_hh,   // [4H,H]
                      const float* __restrict__ b_ih,   // [4H]
                      const float* __restrict__ b_hh,   // [4H]
                      const float* __restrict__ fc_w,   // [1,H]
                      const float* __restrict__ fc_b,   // [1]
                      float* __restrict__ out)          // [B,1]
{
    __shared__ __align__(16) float x_sh[4][TT];
    __shared__ __align__(16) float h_sh[4][2][HH];   // per-warp, double-buffered

    const int tid  = threadIdx.x;
    const int wid  = tid >> 5;
    const int lane = tid & 31;
    const int b    = blockIdx.x * 4 + wid;

    // Stage this warp's x sequence into shared (LDG.128, coalesced per warp).
    {
        const float4* xb4 = reinterpret_cast<const float4*>(x + (size_t)b * TT);
        float4* xs4 = reinterpret_cast<float4*>(x_sh[wid]);
        #pragma unroll
        for (int i = 0; i < TT / 4 / 32; i++)
            xs4[lane + i * 32] = xb4[lane + i * 32];
    }

    // Per-lane weights: gate gt's row (gt*32 + lane), 32 floats = 16 f32x2 pairs.
    u64   w[4][16];
    float wih[4], bias[4];
    #pragma unroll
    for (int gt = 0; gt < 4; gt++) {
        const int row = gt * HH + lane;
        const ulonglong2* wr = reinterpret_cast<const ulonglong2*>(W_hh + row * HH);
        #pragma unroll
        for (int q = 0; q < 8; q++) {
            ulonglong2 v = wr[q];
            w[gt][2 * q]     = v.x;
            w[gt][2 * q + 1] = v.y;
        }
        wih[gt]  = W_ih[row];
        bias[gt] = b_ih[row] + b_hh[row];
    }

    h_sh[wid][0][lane] = 0.0f;
    float c = 0.0f, hj = 0.0f;
    __syncwarp();

    int p = 0;
    for (int t = 0; t < TT; t++) {
        const float xt = x_sh[wid][t];

        // Load h (32 floats) as 8 x 128-bit broadcast LDS -> 16 packed pairs.
        u64 hv[16];
        {
            const ulonglong2* hp = reinterpret_cast<const ulonglong2*>(h_sh[wid][p]);
            #pragma unroll
            for (int q = 0; q < 8; q++) {
                ulonglong2 v = hp[q];
                hv[2 * q]     = v.x;
                hv[2 * q + 1] = v.y;
            }
        }

        // 4 gate dot products, packed 2-wide (64 FFMA2 total).
        float pre[4];
        #pragma unroll
        for (int gt = 0; gt < 4; gt++) {
            u64 a0 = 0ull, a1 = 0ull;   // (0.0f, 0.0f)
            #pragma unroll
            for (int q = 0; q < 8; q++) {
                a0 = fma2(hv[2 * q],     w[gt][2 * q],     a0);
                a1 = fma2(hv[2 * q + 1], w[gt][2 * q + 1], a1);
            }
            pre[gt] = unpack_sum(add2(a0, a1)) + fmaf(xt, wih[gt], bias[gt]);
        }

        const float gi = sigf(pre[0]);
        const float gf = sigf(pre[1]);
        const float gg = tanhx(pre[2]);
        const float go = sigf(pre[3]);

        c  = fmaf(gf, c, gi * gg);
        hj = go * tanhx(c);

        h_sh[wid][p ^ 1][lane] = hj;   // write other buffer: no race with readers of buf p
        p ^= 1;
        __syncwarp();                  // writes visible before next step's reads
    }

    // out[b] = dot(h, fc_w) + fc_b   (warp butterfly reduce)
    float v = hj * fc_w[lane];
    #pragma unroll
    for (int off = 16; off > 0; off >>= 1)
        v += __shfl_xor_sync(0xffffffffu, v, off);
    if (lane == 0) out[b] = v + fc_b[0];
}

extern "C" void kernel_launch(void* const* d_in, const int* in_sizes, int n_in,
                              void* d_out, int out_size) {
    const float* x    = (const float*)d_in[0];
    const float* W_ih = (const float*)d_in[1];
    const float* W_hh = (const float*)d_in[2];
    const float* b_ih = (const float*)d_in[3];
    const float* b_hh = (const float*)d_in[4];
    const float* fc_w = (const float*)d_in[5];
    const float* fc_b = (const float*)d_in[6];
    float* out = (float*)d_out;

    lstm_warp_kernel<<<4096 / 4, 128>>>(x, W_ih, W_hh, b_ih, b_hh, fc_w, fc_b, out);
}

// round 3
// speedup vs baseline: 2.1149x; 1.2360x over previous
#include <cuda_runtime.h>

// LSTM: B=4096, T=512, IN=1, H=32, OUT=1
// One warp handles TWO batch elements (weights shared in registers between
// them -> 2x ILP at same register cost). Lane j computes gate rows
// i_j,f_j,g_j,o_j for both elements. Inner loop: one h-pair load per element
// feeds 16 independent FFMA2 -> deep ILP to hide the activation chain.
// Activations use MUFU.TANH (tanh.approx.f32); sigmoid = 0.5*tanh(x/2)+0.5.

#define TT 512
#define HH 32

typedef unsigned long long u64;

__device__ __forceinline__ u64 fma2(u64 a, u64 b, u64 c) {
    u64 d;
    asm("fma.rn.f32x2 %0, %1, %2, %3;" : "=l"(d) : "l"(a), "l"(b), "l"(c));
    return d;
}
__device__ __forceinline__ u64 add2(u64 a, u64 b) {
    u64 d;
    asm("add.rn.f32x2 %0, %1, %2;" : "=l"(d) : "l"(a), "l"(b));
    return d;
}
__device__ __forceinline__ float unpack_sum(u64 v) {
    float lo, hi;
    asm("mov.b64 {%0, %1}, %2;" : "=f"(lo), "=f"(hi) : "l"(v));
    return lo + hi;
}
__device__ __forceinline__ u64 pack2(float lo, float hi) {
    u64 d;
    asm("mov.b64 %0, {%1, %2};" : "=l"(d) : "f"(lo), "f"(hi));
    return d;
}
__device__ __forceinline__ float tanh_hw(float x) {
    float r;
    asm("tanh.approx.f32 %0, %1;" : "=f"(r) : "f"(x));
    return r;
}
__device__ __forceinline__ float sig_hw(float x) {
    return fmaf(0.5f, tanh_hw(0.5f * x), 0.5f);
}

__global__ __launch_bounds__(128)
void lstm_warp2_kernel(const float* __restrict__ x,      // [B,T,1]
                       const float* __restrict__ W_ih,   // [4H,1]
                       const float* __restrict__ W_hh,   // [4H,H]
                       const float* __restrict__ b_ih,   // [4H]
                       const float* __restrict__ b_hh,   // [4H]
                       const float* __restrict__ fc_w,   // [1,H]
                       const float* __restrict__ fc_b,   // [1]
                       float* __restrict__ out)          // [B,1]
{
    __shared__ __align__(16) float x_sh[8][TT];           // 8 elements per CTA
    __shared__ __align__(16) float h_sh[4][2][2][HH];     // [warp][buf][elem][j]

    const int tid  = threadIdx.x;
    const int wid  = tid >> 5;
    const int lane = tid & 31;
    const int b0   = blockIdx.x * 8 + wid * 2;            // this warp's elements: b0, b0+1

    // Stage both x sequences (coalesced LDG.128 per warp).
    #pragma unroll
    for (int e = 0; e < 2; e++) {
        const float4* xb4 = reinterpret_cast<const float4*>(x + (size_t)(b0 + e) * TT);
        float4* xs4 = reinterpret_cast<float4*>(x_sh[wid * 2 + e]);
        #pragma unroll
        for (int i = 0; i < TT / 4 / 32; i++)
            xs4[lane + i * 32] = xb4[lane + i * 32];
    }

    // Per-lane weights (shared by both elements): 4 gate rows x 16 f32x2 pairs.
    u64   w[4][16];
    float wih[4], bias[4];
    #pragma unroll
    for (int gt = 0; gt < 4; gt++) {
        const int row = gt * HH + lane;
        const ulonglong2* wr = reinterpret_cast<const ulonglong2*>(W_hh + row * HH);
        #pragma unroll
        for (int q = 0; q < 8; q++) {
            ulonglong2 v = wr[q];
            w[gt][2 * q]     = v.x;
            w[gt][2 * q + 1] = v.y;
        }
        wih[gt]  = W_ih[row];
        bias[gt] = b_ih[row] + b_hh[row];
    }

    h_sh[wid][0][0][lane] = 0.0f;
    h_sh[wid][0][1][lane] = 0.0f;
    float c0 = 0.f, c1 = 0.f, hj0 = 0.f, hj1 = 0.f;
    __syncwarp();

    int p = 0;
    for (int t = 0; t < TT; t++) {
        const float xt0 = x_sh[wid * 2 + 0][t];
        const float xt1 = x_sh[wid * 2 + 1][t];

        // Accumulators: [elem][gate][chain] ; fold x*W_ih + bias into init.
        u64 acc[2][4][2];
        #pragma unroll
        for (int gt = 0; gt < 4; gt++) {
            acc[0][gt][0] = pack2(fmaf(xt0, wih[gt], bias[gt]), 0.f);
            acc[1][gt][0] = pack2(fmaf(xt1, wih[gt], bias[gt]), 0.f);
            acc[0][gt][1] = 0ull;
            acc[1][gt][1] = 0ull;
        }

        const ulonglong2* hp0 = reinterpret_cast<const ulonglong2*>(h_sh[wid][p][0]);
        const ulonglong2* hp1 = reinterpret_cast<const ulonglong2*>(h_sh[wid][p][1]);

        #pragma unroll
        for (int q = 0; q < 8; q++) {
            ulonglong2 ha = hp0[q];   // broadcast LDS.128
            ulonglong2 hb = hp1[q];
            #pragma unroll
            for (int gt = 0; gt < 4; gt++) {
                acc[0][gt][0] = fma2(ha.x, w[gt][2 * q],     acc[0][gt][0]);
                acc[0][gt][1] = fma2(ha.y, w[gt][2 * q + 1], acc[0][gt][1]);
                acc[1][gt][0] = fma2(hb.x, w[gt][2 * q],     acc[1][gt][0]);
                acc[1][gt][1] = fma2(hb.y, w[gt][2 * q + 1], acc[1][gt][1]);
            }
        }

        float pre0[4], pre1[4];
        #pragma unroll
        for (int gt = 0; gt < 4; gt++) {
            pre0[gt] = unpack_sum(add2(acc[0][gt][0], acc[0][gt][1]));
            pre1[gt] = unpack_sum(add2(acc[1][gt][0], acc[1][gt][1]));
        }

        // Element 0
        {
            const float gi = sig_hw(pre0[0]);
            const float gf = sig_hw(pre0[1]);
            const float gg = tanh_hw(pre0[2]);
            const float go = sig_hw(pre0[3]);
            c0  = fmaf(gf, c0, gi * gg);
            hj0 = go * tanh_hw(c0);
            h_sh[wid][p ^ 1][0][lane] = hj0;
        }
        // Element 1 (independent -> scheduler overlaps with elem 0's chain)
        {
            const float gi = sig_hw(pre1[0]);
            const float gf = sig_hw(pre1[1]);
            const float gg = tanh_hw(pre1[2]);
            const float go = sig_hw(pre1[3]);
            c1  = fmaf(gf, c1, gi * gg);
            hj1 = go * tanh_hw(c1);
            h_sh[wid][p ^ 1][1][lane] = hj1;
        }

        p ^= 1;
        __syncwarp();
    }

    // out[b] = dot(h, fc_w) + fc_b for both elements.
    const float fw = fc_w[lane];
    float v0 = hj0 * fw;
    float v1 = hj1 * fw;
    #pragma unroll
    for (int off = 16; off > 0; off >>= 1) {
        v0 += __shfl_xor_sync(0xffffffffu, v0, off);
        v1 += __shfl_xor_sync(0xffffffffu, v1, off);
    }
    if (lane == 0) {
        out[b0]     = v0 + fc_b[0];
        out[b0 + 1] = v1 + fc_b[0];
    }
}

extern "C" void kernel_launch(void* const* d_in, const int* in_sizes, int n_in,
                              void* d_out, int out_size) {
    const float* x    = (const float*)d_in[0];
    const float* W_ih = (const float*)d_in[1];
    const float* W_hh = (const float*)d_in[2];
    const float* b_ih = (const float*)d_in[3];
    const float* b_hh = (const float*)d_in[4];
    const float* fc_w = (const float*)d_in[5];
    const float* fc_b = (const float*)d_in[6];
    float* out = (float*)d_out;

    lstm_warp2_kernel<<<4096 / 8, 128>>>(x, W_ih, W_hh, b_ih, b_hh, fc_w, fc_b, out);
}